// round 9
// baseline (speedup 1.0000x reference)
#include <cuda_runtime.h>
#include <cuda_bf16.h>
#include <mma.h>

using namespace nvcuda;

#define N_NODES 50000
#define N_EDGES 800000
#define N_GRAPHS 512
#define IN_CH 128
#define HID 64
#define EQ (N_EDGES / 4)

// ---------------- scratch (device globals) ----------------
__device__ float g_xw[N_NODES * HID];
__device__ float g_h1[N_NODES * HID];
__device__ float g_h2[N_NODES * HID];
__device__ float g_h3[N_NODES * HID];
__device__ float g_deg[N_NODES];
__device__ float g_dinv[N_NODES];
__device__ float g_coef[N_EDGES];
__device__ float g_pool[N_GRAPHS * HID];
__device__ float g_cnt[N_GRAPHS];

__device__ __forceinline__ void red_add_v4(float* addr, float a, float b,
                                           float c, float d) {
    asm volatile("red.global.add.v4.f32 [%0], {%1, %2, %3, %4};"
                 :: "l"(addr), "f"(a), "f"(b), "f"(c), "f"(d) : "memory");
}

// ---------------- degree / norm (side stream) ----------------
__global__ void deg_kernel(const int* __restrict__ dst,
                           const float* __restrict__ ew) {
    int e = blockIdx.x * blockDim.x + threadIdx.x;
    if (e < N_EDGES) atomicAdd(&g_deg[dst[e]], ew[e]);
}

__global__ void dinv_kernel() {
    int i = blockIdx.x * blockDim.x + threadIdx.x;
    if (i < N_NODES) g_dinv[i] = rsqrtf(g_deg[i] + 1.0f);
}

__global__ void coef_kernel(const int* __restrict__ src,
                            const int* __restrict__ dst,
                            const float* __restrict__ ew) {
    int e = blockIdx.x * blockDim.x + threadIdx.x;
    if (e < N_EDGES)
        g_coef[e] = g_dinv[src[e]] * ew[e] * g_dinv[dst[e]];
}

// ---------------- GEMM 1 (tf32 wmma): [N,128]@[128,64] -> g_xw --------------
// block = 256 threads (8 warps). Tile 64 rows x 64 cols.
// warp w: rows (w>>1)*16, cols (w&1)*32 (two 16x16 subtiles).
#define TM 64
__global__ void __launch_bounds__(256) gemm1_kernel(const float* __restrict__ x,
                                                    const float* __restrict__ W) {
    extern __shared__ float sm[];
    float* Ws = sm;                    // [128*64] tf32
    float* Xs = sm + IN_CH * HID;      // [64*128] tf32 (reused as Cs[64*64])
    int tid = threadIdx.x;
    int wid = tid >> 5;
    int row0 = blockIdx.x * TM;

    for (int i = tid; i < IN_CH * HID / 4; i += 256) {
        float4 v = *(const float4*)&W[i * 4];
        v.x = wmma::__float_to_tf32(v.x); v.y = wmma::__float_to_tf32(v.y);
        v.z = wmma::__float_to_tf32(v.z); v.w = wmma::__float_to_tf32(v.w);
        *(float4*)&Ws[i * 4] = v;
    }
    for (int i = tid; i < TM * (IN_CH / 4); i += 256) {
        int r  = i >> 5;
        int c4 = (i & 31) * 4;
        int node = row0 + r;
        float4 v = (node < N_NODES)
                 ? *(const float4*)&x[(long long)node * IN_CH + c4]
                 : make_float4(0.f, 0.f, 0.f, 0.f);
        v.x = wmma::__float_to_tf32(v.x); v.y = wmma::__float_to_tf32(v.y);
        v.z = wmma::__float_to_tf32(v.z); v.w = wmma::__float_to_tf32(v.w);
        *(float4*)&Xs[r * IN_CH + c4] = v;
    }
    __syncthreads();

    int rowbase = (wid >> 1) * 16;
    int colbase = (wid & 1) * 32;

    wmma::fragment<wmma::matrix_a, 16, 16, 8, wmma::precision::tf32, wmma::row_major> a;
    wmma::fragment<wmma::matrix_b, 16, 16, 8, wmma::precision::tf32, wmma::row_major> b0, b1;
    wmma::fragment<wmma::accumulator, 16, 16, 8, float> c0, c1;
    wmma::fill_fragment(c0, 0.0f);
    wmma::fill_fragment(c1, 0.0f);

    #pragma unroll
    for (int kk = 0; kk < IN_CH; kk += 8) {
        wmma::load_matrix_sync(a, &Xs[rowbase * IN_CH + kk], IN_CH);
        wmma::load_matrix_sync(b0, &Ws[kk * HID + colbase], HID);
        wmma::load_matrix_sync(b1, &Ws[kk * HID + colbase + 16], HID);
        wmma::mma_sync(c0, a, b0, c0);
        wmma::mma_sync(c1, a, b1, c1);
    }

    // stage result through smem (guarded boundary stores)
    __syncthreads();
    float* Cs = Xs;   // 64x64
    wmma::store_matrix_sync(&Cs[rowbase * TM + colbase], c0, TM, wmma::mem_row_major);
    wmma::store_matrix_sync(&Cs[rowbase * TM + colbase + 16], c1, TM, wmma::mem_row_major);
    __syncthreads();
    for (int i = tid; i < TM * (HID / 4); i += 256) {
        int r  = i >> 4;
        int c4 = (i & 15) * 4;
        int node = row0 + r;
        if (node < N_NODES)
            *(float4*)&g_xw[node * HID + c4] = *(const float4*)&Cs[r * TM + c4];
    }
}

// ---------------- self-loop + bias init: h1 = dinv^2*xw + b ----------------
__global__ void init1_kernel(const float* __restrict__ b) {
    int idx = blockIdx.x * blockDim.x + threadIdx.x;
    if (idx < N_NODES * 16) {
        int node = idx >> 4;
        int c4   = (idx & 15) * 4;
        float di = g_dinv[node];
        float dd = di * di;
        float4 v  = *(const float4*)&g_xw[node * HID + c4];
        float4 bb = *(const float4*)&b[c4];
        float4 h = make_float4(dd*v.x + bb.x, dd*v.y + bb.y,
                               dd*v.z + bb.z, dd*v.w + bb.w);
        *(float4*)&g_h1[node * HID + c4] = h;
    }
}

// ---------------- GEMM 2 (tf32 wmma): relu(g_h1)@W2 -> g_h2, g_h3 -----------
__global__ void __launch_bounds__(256) gemm2_kernel(const float* __restrict__ W,
                                                    const float* __restrict__ b) {
    __shared__ float Ws[HID * HID];    // 16 KB
    __shared__ float Xs[TM * HID];     // 16 KB (reused as Cs)
    int tid = threadIdx.x;
    int wid = tid >> 5;
    int row0 = blockIdx.x * TM;

    for (int i = tid; i < HID * HID / 4; i += 256) {
        float4 v = *(const float4*)&W[i * 4];
        v.x = wmma::__float_to_tf32(v.x); v.y = wmma::__float_to_tf32(v.y);
        v.z = wmma::__float_to_tf32(v.z); v.w = wmma::__float_to_tf32(v.w);
        *(float4*)&Ws[i * 4] = v;
    }
    for (int i = tid; i < TM * (HID / 4); i += 256) {
        int r  = i >> 4;
        int c4 = (i & 15) * 4;
        int node = row0 + r;
        float4 v = make_float4(0.f, 0.f, 0.f, 0.f);
        if (node < N_NODES) {
            float4 t = *(const float4*)&g_h1[node * HID + c4];
            v.x = wmma::__float_to_tf32(fmaxf(t.x, 0.f));
            v.y = wmma::__float_to_tf32(fmaxf(t.y, 0.f));
            v.z = wmma::__float_to_tf32(fmaxf(t.z, 0.f));
            v.w = wmma::__float_to_tf32(fmaxf(t.w, 0.f));
        }
        *(float4*)&Xs[r * HID + c4] = v;
    }
    __syncthreads();

    int rowbase = (wid >> 1) * 16;
    int colbase = (wid & 1) * 32;

    wmma::fragment<wmma::matrix_a, 16, 16, 8, wmma::precision::tf32, wmma::row_major> a;
    wmma::fragment<wmma::matrix_b, 16, 16, 8, wmma::precision::tf32, wmma::row_major> b0, b1;
    wmma::fragment<wmma::accumulator, 16, 16, 8, float> c0, c1;
    wmma::fill_fragment(c0, 0.0f);
    wmma::fill_fragment(c1, 0.0f);

    #pragma unroll
    for (int kk = 0; kk < HID; kk += 8) {
        wmma::load_matrix_sync(a, &Xs[rowbase * HID + kk], HID);
        wmma::load_matrix_sync(b0, &Ws[kk * HID + colbase], HID);
        wmma::load_matrix_sync(b1, &Ws[kk * HID + colbase + 16], HID);
        wmma::mma_sync(c0, a, b0, c0);
        wmma::mma_sync(c1, a, b1, c1);
    }

    __syncthreads();
    float* Cs = Xs;
    wmma::store_matrix_sync(&Cs[rowbase * TM + colbase], c0, TM, wmma::mem_row_major);
    wmma::store_matrix_sync(&Cs[rowbase * TM + colbase + 16], c1, TM, wmma::mem_row_major);
    __syncthreads();
    for (int i = tid; i < TM * (HID / 4); i += 256) {
        int r  = i >> 4;
        int c4 = (i & 15) * 4;
        int node = row0 + r;
        if (node < N_NODES) {
            float4 acc = *(const float4*)&Cs[r * TM + c4];
            *(float4*)&g_h2[node * HID + c4] = acc;
            float di = g_dinv[node];
            float dd = di * di;
            float4 bb = *(const float4*)&b[c4];
            float4 h = make_float4(dd*acc.x + bb.x, dd*acc.y + bb.y,
                                   dd*acc.z + bb.z, dd*acc.w + bb.w);
            *(float4*)&g_h3[node * HID + c4] = h;
        }
    }
}

// ---------------- edge scatter: 4 independent edges per thread --------------
__global__ void scatter_kernel(const int* __restrict__ src,
                               const int* __restrict__ dst,
                               const float* __restrict__ in,
                               float* __restrict__ out) {
    int idx = blockIdx.x * blockDim.x + threadIdx.x;   // < EQ*16 = 3.2M
    if (idx >= EQ * 16) return;
    int e0 = idx >> 4;
    int c4 = (idx & 15) * 4;

    int   e[4];
    float cf[4];
    int   s[4], d[4];
    #pragma unroll
    for (int j = 0; j < 4; j++) {
        e[j]  = e0 + j * EQ;
        cf[j] = g_coef[e[j]];
        s[j]  = src[e[j]];
        d[j]  = dst[e[j]];
    }
    float4 v[4];
    #pragma unroll
    for (int j = 0; j < 4; j++)
        v[j] = *(const float4*)(in + (long long)s[j] * HID + c4);
    #pragma unroll
    for (int j = 0; j < 4; j++)
        red_add_v4(out + (long long)d[j] * HID + c4,
                   cf[j] * v[j].x, cf[j] * v[j].y,
                   cf[j] * v[j].z, cf[j] * v[j].w);
}

// ---------------- pooling ----------------
__global__ void pool_kernel(const int* __restrict__ batch) {
    int idx = blockIdx.x * blockDim.x + threadIdx.x;
    if (idx < N_NODES * 16) {
        int i  = idx >> 4;
        int c4 = (idx & 15) * 4;
        int g = batch[i];
        float4 v = *(const float4*)&g_h3[i * HID + c4];
        red_add_v4(&g_pool[g * HID + c4], v.x, v.y, v.z, v.w);
        if (c4 == 0) atomicAdd(&g_cnt[g], 1.0f);
    }
}

// ---------------- head ----------------
__global__ void head_kernel(const float* __restrict__ LW1,
                            const float* __restrict__ Lb1,
                            const float* __restrict__ LW2,
                            const float* __restrict__ Lb2,
                            float* __restrict__ out) {
    int g = blockIdx.x;
    int t = threadIdx.x;
    __shared__ float p[HID];
    __shared__ float h[32];
    float cnt = fmaxf(g_cnt[g], 1.0f);
    p[t]      = g_pool[g * HID + t] / cnt;
    p[t + 32] = g_pool[g * HID + 32 + t] / cnt;
    __syncwarp();
    float acc = Lb1[t];
    #pragma unroll
    for (int k = 0; k < HID; k++) acc += p[k] * LW1[k * 32 + t];
    h[t] = acc;
    __syncwarp();
    if (t < 10) {
        float o = Lb2[t];
        #pragma unroll
        for (int j = 0; j < 32; j++) o += h[j] * LW2[j * 10 + t];
        out[g * 10 + t] = o;
    }
}

// ---------------- launch ----------------
extern "C" void kernel_launch(void* const* d_in, const int* in_sizes, int n_in,
                              void* d_out, int out_size) {
    const float* x     = (const float*)d_in[0];
    const int*   ei    = (const int*)d_in[1];
    const float* ew    = (const float*)d_in[2];
    const int*   batch = (const int*)d_in[3];
    const float* W1    = (const float*)d_in[4];
    const float* b1    = (const float*)d_in[5];
    const float* W2    = (const float*)d_in[6];
    const float* b2    = (const float*)d_in[7];
    const float* LW1   = (const float*)d_in[8];
    const float* Lb1   = (const float*)d_in[9];
    const float* LW2   = (const float*)d_in[10];
    const float* Lb2   = (const float*)d_in[11];
    float* out = (float*)d_out;

    const int* src = ei;
    const int* dst = ei + N_EDGES;

    void *p_deg, *p_pool, *p_cnt;
    cudaGetSymbolAddress(&p_deg,  g_deg);
    cudaGetSymbolAddress(&p_pool, g_pool);
    cudaGetSymbolAddress(&p_cnt,  g_cnt);

    float *xw, *h1, *h2, *h3;
    cudaGetSymbolAddress((void**)&xw, g_xw);
    cudaGetSymbolAddress((void**)&h1, g_h1);
    cudaGetSymbolAddress((void**)&h2, g_h2);
    cudaGetSymbolAddress((void**)&h3, g_h3);

    const int SM1_BYTES = (IN_CH * HID + TM * IN_CH) * (int)sizeof(float); // 64 KB

    static cudaStream_t s1 = nullptr;
    static cudaEvent_t evFork = nullptr, evJoin = nullptr;
    static bool init_done = false;
    if (!init_done) {
        cudaStreamCreateWithFlags(&s1, cudaStreamNonBlocking);
        cudaEventCreateWithFlags(&evFork, cudaEventDisableTiming);
        cudaEventCreateWithFlags(&evJoin, cudaEventDisableTiming);
        cudaFuncSetAttribute(gemm1_kernel,
                             cudaFuncAttributeMaxDynamicSharedMemorySize,
                             SM1_BYTES);
        cudaFuncSetAttribute(gemm1_kernel,
                             cudaFuncAttributePreferredSharedMemoryCarveout, 100);
        cudaFuncSetAttribute(gemm2_kernel,
                             cudaFuncAttributePreferredSharedMemoryCarveout, 100);
        init_done = true;
    }

    // ---- fork: prep chain on s1 runs concurrently with gemm1 on stream 0 ----
    cudaEventRecord(evFork, 0);
    cudaStreamWaitEvent(s1, evFork, 0);

    cudaMemsetAsync(p_deg,  0, N_NODES * sizeof(float), s1);
    cudaMemsetAsync(p_pool, 0, N_GRAPHS * HID * sizeof(float), s1);
    cudaMemsetAsync(p_cnt,  0, N_GRAPHS * sizeof(float), s1);
    deg_kernel<<<(N_EDGES + 255) / 256, 256, 0, s1>>>(dst, ew);
    dinv_kernel<<<(N_NODES + 255) / 256, 256, 0, s1>>>();
    coef_kernel<<<(N_EDGES + 255) / 256, 256, 0, s1>>>(src, dst, ew);
    cudaEventRecord(evJoin, s1);

    int gblocks = (N_NODES + TM - 1) / TM;
    gemm1_kernel<<<gblocks, 256, SM1_BYTES>>>(x, W1);   // no dinv dependency

    cudaStreamWaitEvent(0, evJoin, 0);                  // join before dinv users

    init1_kernel<<<(N_NODES * 16 + 255) / 256, 256>>>(b1);
    scatter_kernel<<<(EQ * 16 + 255) / 256, 256>>>(src, dst, xw, h1);

    gemm2_kernel<<<gblocks, 256>>>(W2, b2);
    scatter_kernel<<<(EQ * 16 + 255) / 256, 256>>>(src, dst, h2, h3);

    pool_kernel<<<(N_NODES * 16 + 255) / 256, 256>>>(batch);
    head_kernel<<<N_GRAPHS, 32>>>(LW1, Lb1, LW2, Lb2, out);
}

// round 10
// speedup vs baseline: 1.0914x; 1.0914x over previous
#include <cuda_runtime.h>
#include <cuda_bf16.h>

#define N_NODES 50000
#define N_EDGES 800000
#define N_GRAPHS 512
#define IN_CH 128
#define HID 64
#define EQ (N_EDGES / 4)

// ---------------- scratch (device globals) ----------------
__device__ float g_xw[N_NODES * HID];
__device__ float g_h1[N_NODES * HID];
__device__ float g_h2[N_NODES * HID];
__device__ float g_h3[N_NODES * HID];
__device__ float g_deg[N_NODES];
__device__ float g_dinv[N_NODES];
__device__ float g_coef[N_EDGES];
__device__ float g_pool[N_GRAPHS * HID];
__device__ float g_cnt[N_GRAPHS];

__device__ __forceinline__ void red_add_v4(float* addr, float a, float b,
                                           float c, float d) {
    asm volatile("red.global.add.v4.f32 [%0], {%1, %2, %3, %4};"
                 :: "l"(addr), "f"(a), "f"(b), "f"(c), "f"(d) : "memory");
}

// ---------------- degree / norm (side stream) ----------------
__global__ void deg_kernel(const int* __restrict__ dst,
                           const float* __restrict__ ew) {
    int e = blockIdx.x * blockDim.x + threadIdx.x;
    if (e < N_EDGES) atomicAdd(&g_deg[dst[e]], ew[e]);
}

__global__ void dinv_kernel() {
    int i = blockIdx.x * blockDim.x + threadIdx.x;
    if (i < N_NODES) g_dinv[i] = rsqrtf(g_deg[i] + 1.0f);
}

__global__ void coef_kernel(const int* __restrict__ src,
                            const int* __restrict__ dst,
                            const float* __restrict__ ew) {
    int e = blockIdx.x * blockDim.x + threadIdx.x;
    if (e < N_EDGES)
        g_coef[e] = g_dinv[src[e]] * ew[e] * g_dinv[dst[e]];
}

// ---------------- GEMM 1 (fp32): [N,128]@[128,64] -> g_xw -------------------
#define TM 64
#define KH 64
__global__ void __launch_bounds__(256) gemm1_kernel(const float* __restrict__ x,
                                                    const float* __restrict__ W) {
    __shared__ float Ws[KH * HID];       // 16 KB
    __shared__ float Xs[TM * IN_CH];     // 32 KB
    int tid = threadIdx.x;
    int row0 = blockIdx.x * TM;

    for (int i = tid; i < TM * (IN_CH / 4); i += 256) {
        int r  = i >> 5;
        int c4 = (i & 31) * 4;
        int node = row0 + r;
        float4 v = (node < N_NODES)
                 ? *(const float4*)&x[(long long)node * IN_CH + c4]
                 : make_float4(0.f, 0.f, 0.f, 0.f);
        *(float4*)&Xs[r * IN_CH + c4] = v;
    }

    int ty = tid >> 4;
    int tx = tid & 15;
    float4 acc0 = make_float4(0,0,0,0), acc1 = acc0, acc2 = acc0, acc3 = acc0;
    const float* xrow = &Xs[(ty * 4) * IN_CH];

    #pragma unroll
    for (int half = 0; half < 2; half++) {
        __syncthreads();
        for (int i = tid; i < KH * HID / 4; i += 256)
            *(float4*)&Ws[i * 4] = *(const float4*)&W[half * KH * HID + i * 4];
        __syncthreads();
        int kb = half * KH;
        #pragma unroll 4
        for (int k = 0; k < KH; k++) {
            float4 w = *(const float4*)&Ws[k * HID + tx * 4];
            float x0 = xrow[kb + k];
            float x1 = xrow[IN_CH + kb + k];
            float x2 = xrow[2 * IN_CH + kb + k];
            float x3 = xrow[3 * IN_CH + kb + k];
            acc0.x += x0*w.x; acc0.y += x0*w.y; acc0.z += x0*w.z; acc0.w += x0*w.w;
            acc1.x += x1*w.x; acc1.y += x1*w.y; acc1.z += x1*w.z; acc1.w += x1*w.w;
            acc2.x += x2*w.x; acc2.y += x2*w.y; acc2.z += x2*w.z; acc2.w += x2*w.w;
            acc3.x += x3*w.x; acc3.y += x3*w.y; acc3.z += x3*w.z; acc3.w += x3*w.w;
        }
    }

    float4 accs[4] = {acc0, acc1, acc2, acc3};
    #pragma unroll
    for (int i = 0; i < 4; i++) {
        int node = row0 + ty * 4 + i;
        if (node < N_NODES)
            *(float4*)&g_xw[node * HID + tx * 4] = accs[i];
    }
}

// ---------------- self-loop + bias init: h1 = dinv^2*xw + b ----------------
__global__ void init1_kernel(const float* __restrict__ b) {
    int idx = blockIdx.x * blockDim.x + threadIdx.x;
    if (idx < N_NODES * 16) {
        int node = idx >> 4;
        int c4   = (idx & 15) * 4;
        float di = g_dinv[node];
        float dd = di * di;
        float4 v  = *(const float4*)&g_xw[node * HID + c4];
        float4 bb = *(const float4*)&b[c4];
        float4 h = make_float4(dd*v.x + bb.x, dd*v.y + bb.y,
                               dd*v.z + bb.z, dd*v.w + bb.w);
        *(float4*)&g_h1[node * HID + c4] = h;
    }
}

// ---------------- GEMM 2 (fp32): relu(g_h1)@W2 -> g_h2, g_h3 ----------------
__global__ void __launch_bounds__(256) gemm2_kernel(const float* __restrict__ W,
                                                    const float* __restrict__ b) {
    __shared__ float Ws[HID * HID];
    __shared__ float Xs[TM * HID];
    int tid = threadIdx.x;
    int row0 = blockIdx.x * TM;

    for (int i = tid; i < HID * HID / 4; i += 256)
        *(float4*)&Ws[i * 4] = *(const float4*)&W[i * 4];
    for (int i = tid; i < TM * (HID / 4); i += 256) {
        int r  = i >> 4;
        int c4 = (i & 15) * 4;
        int node = row0 + r;
        float4 v = make_float4(0.f, 0.f, 0.f, 0.f);
        if (node < N_NODES) {
            float4 t = *(const float4*)&g_h1[node * HID + c4];
            v = make_float4(fmaxf(t.x, 0.f), fmaxf(t.y, 0.f),
                            fmaxf(t.z, 0.f), fmaxf(t.w, 0.f));
        }
        *(float4*)&Xs[r * HID + c4] = v;
    }
    __syncthreads();

    int ty = tid >> 4;
    int tx = tid & 15;
    float4 acc0 = make_float4(0,0,0,0), acc1 = acc0, acc2 = acc0, acc3 = acc0;
    const float* xrow = &Xs[(ty * 4) * HID];
    #pragma unroll 4
    for (int k = 0; k < HID; k++) {
        float4 w = *(const float4*)&Ws[k * HID + tx * 4];
        float x0 = xrow[k];
        float x1 = xrow[HID + k];
        float x2 = xrow[2 * HID + k];
        float x3 = xrow[3 * HID + k];
        acc0.x += x0*w.x; acc0.y += x0*w.y; acc0.z += x0*w.z; acc0.w += x0*w.w;
        acc1.x += x1*w.x; acc1.y += x1*w.y; acc1.z += x1*w.z; acc1.w += x1*w.w;
        acc2.x += x2*w.x; acc2.y += x2*w.y; acc2.z += x2*w.z; acc2.w += x2*w.w;
        acc3.x += x3*w.x; acc3.y += x3*w.y; acc3.z += x3*w.z; acc3.w += x3*w.w;
    }
    float4 bb = *(const float4*)&b[tx * 4];
    float4 accs[4] = {acc0, acc1, acc2, acc3};
    #pragma unroll
    for (int i = 0; i < 4; i++) {
        int node = row0 + ty * 4 + i;
        if (node < N_NODES) {
            *(float4*)&g_h2[node * HID + tx * 4] = accs[i];
            float di = g_dinv[node];
            float dd = di * di;
            float4 h = make_float4(dd*accs[i].x + bb.x, dd*accs[i].y + bb.y,
                                   dd*accs[i].z + bb.z, dd*accs[i].w + bb.w);
            *(float4*)&g_h3[node * HID + tx * 4] = h;
        }
    }
}

// ---------------- edge scatter: 4 independent edges per thread --------------
// 16 threads cover one float4 lane of 4 edges (e0 + j*EQ). All gathers are
// issued before any RED so 4 LDG.128s are in flight per thread.
__global__ void __launch_bounds__(256) scatter_kernel(const int* __restrict__ src,
                                                      const int* __restrict__ dst,
                                                      const float* __restrict__ in,
                                                      float* __restrict__ out) {
    int idx = blockIdx.x * blockDim.x + threadIdx.x;   // < EQ*16 = 3.2M
    if (idx >= EQ * 16) return;
    int e0 = idx >> 4;
    int c4 = (idx & 15) * 4;

    float cf[4];
    int   s[4], d[4];
    #pragma unroll
    for (int j = 0; j < 4; j++) {
        int e = e0 + j * EQ;
        cf[j] = g_coef[e];
        s[j]  = src[e];
        d[j]  = dst[e];
    }
    float4 v[4];
    #pragma unroll
    for (int j = 0; j < 4; j++)
        v[j] = *(const float4*)(in + (long long)s[j] * HID + c4);
    #pragma unroll
    for (int j = 0; j < 4; j++)
        red_add_v4(out + (long long)d[j] * HID + c4,
                   cf[j] * v[j].x, cf[j] * v[j].y,
                   cf[j] * v[j].z, cf[j] * v[j].w);
}

// ---------------- pooling ----------------
__global__ void pool_kernel(const int* __restrict__ batch) {
    int idx = blockIdx.x * blockDim.x + threadIdx.x;
    if (idx < N_NODES * 16) {
        int i  = idx >> 4;
        int c4 = (idx & 15) * 4;
        int g = batch[i];
        float4 v = *(const float4*)&g_h3[i * HID + c4];
        red_add_v4(&g_pool[g * HID + c4], v.x, v.y, v.z, v.w);
        if (c4 == 0) atomicAdd(&g_cnt[g], 1.0f);
    }
}

// ---------------- head ----------------
__global__ void head_kernel(const float* __restrict__ LW1,
                            const float* __restrict__ Lb1,
                            const float* __restrict__ LW2,
                            const float* __restrict__ Lb2,
                            float* __restrict__ out) {
    int g = blockIdx.x;
    int t = threadIdx.x;
    __shared__ float p[HID];
    __shared__ float h[32];
    float cnt = fmaxf(g_cnt[g], 1.0f);
    p[t]      = g_pool[g * HID + t] / cnt;
    p[t + 32] = g_pool[g * HID + 32 + t] / cnt;
    __syncwarp();
    float acc = Lb1[t];
    #pragma unroll
    for (int k = 0; k < HID; k++) acc += p[k] * LW1[k * 32 + t];
    h[t] = acc;
    __syncwarp();
    if (t < 10) {
        float o = Lb2[t];
        #pragma unroll
        for (int j = 0; j < 32; j++) o += h[j] * LW2[j * 10 + t];
        out[g * 10 + t] = o;
    }
}

// ---------------- launch ----------------
extern "C" void kernel_launch(void* const* d_in, const int* in_sizes, int n_in,
                              void* d_out, int out_size) {
    const float* x     = (const float*)d_in[0];
    const int*   ei    = (const int*)d_in[1];
    const float* ew    = (const float*)d_in[2];
    const int*   batch = (const int*)d_in[3];
    const float* W1    = (const float*)d_in[4];
    const float* b1    = (const float*)d_in[5];
    const float* W2    = (const float*)d_in[6];
    const float* b2    = (const float*)d_in[7];
    const float* LW1   = (const float*)d_in[8];
    const float* Lb1   = (const float*)d_in[9];
    const float* LW2   = (const float*)d_in[10];
    const float* Lb2   = (const float*)d_in[11];
    float* out = (float*)d_out;

    const int* src = ei;
    const int* dst = ei + N_EDGES;

    void *p_deg, *p_pool, *p_cnt;
    cudaGetSymbolAddress(&p_deg,  g_deg);
    cudaGetSymbolAddress(&p_pool, g_pool);
    cudaGetSymbolAddress(&p_cnt,  g_cnt);

    float *xw, *h1, *h2, *h3;
    cudaGetSymbolAddress((void**)&xw, g_xw);
    cudaGetSymbolAddress((void**)&h1, g_h1);
    cudaGetSymbolAddress((void**)&h2, g_h2);
    cudaGetSymbolAddress((void**)&h3, g_h3);

    static cudaStream_t s1 = nullptr;
    static cudaEvent_t evFork = nullptr, evJoin = nullptr;
    static bool init_done = false;
    if (!init_done) {
        cudaStreamCreateWithFlags(&s1, cudaStreamNonBlocking);
        cudaEventCreateWithFlags(&evFork, cudaEventDisableTiming);
        cudaEventCreateWithFlags(&evJoin, cudaEventDisableTiming);
        cudaFuncSetAttribute(gemm1_kernel,
                             cudaFuncAttributePreferredSharedMemoryCarveout, 100);
        cudaFuncSetAttribute(gemm2_kernel,
                             cudaFuncAttributePreferredSharedMemoryCarveout, 100);
        init_done = true;
    }

    // ---- fork: prep chain on s1 runs concurrently with gemm1 on stream 0 ----
    cudaEventRecord(evFork, 0);
    cudaStreamWaitEvent(s1, evFork, 0);

    cudaMemsetAsync(p_deg,  0, N_NODES * sizeof(float), s1);
    cudaMemsetAsync(p_pool, 0, N_GRAPHS * HID * sizeof(float), s1);
    cudaMemsetAsync(p_cnt,  0, N_GRAPHS * sizeof(float), s1);
    deg_kernel<<<(N_EDGES + 255) / 256, 256, 0, s1>>>(dst, ew);
    dinv_kernel<<<(N_NODES + 255) / 256, 256, 0, s1>>>();
    coef_kernel<<<(N_EDGES + 255) / 256, 256, 0, s1>>>(src, dst, ew);
    cudaEventRecord(evJoin, s1);

    int gblocks = (N_NODES + TM - 1) / TM;
    gemm1_kernel<<<gblocks, 256>>>(x, W1);          // pure GEMM, no dinv dep

    cudaStreamWaitEvent(0, evJoin, 0);              // join before dinv users

    init1_kernel<<<(N_NODES * 16 + 255) / 256, 256>>>(b1);
    scatter_kernel<<<(EQ * 16 + 255) / 256, 256>>>(src, dst, xw, h1);

    gemm2_kernel<<<gblocks, 256>>>(W2, b2);
    scatter_kernel<<<(EQ * 16 + 255) / 256, 256>>>(src, dst, h2, h3);

    pool_kernel<<<(N_NODES * 16 + 255) / 256, 256>>>(batch);
    head_kernel<<<N_GRAPHS, 32>>>(LW1, Lb1, LW2, Lb2, out);
}